// round 5
// baseline (speedup 1.0000x reference)
#include <cuda_runtime.h>
#include <math.h>

#define HID     256
#define SLOTS   64
#define NB      4
#define TSTEPS  256
#define BATCH   512
#define WSROWS  128          // W_update rows cached in SMEM
#define WSTRIDE 260          // 256 + 4 floats pad -> conflict-free LDS.128
#define NTH     256
#define EPSV    1e-5f

// Slot-memory scratch: 512 batches x 64 slots x 256 hid = 32 MB (L2-resident)
__device__ float g_mem[(size_t)BATCH * SLOTS * HID];

__global__ void __launch_bounds__(NTH, 1)
postnorm_rnn_kernel(const float* __restrict__ x,        // [512,256,1]
                    const float* __restrict__ W_embed,  // [256]
                    const float* __restrict__ b_embed,  // [256]
                    const float* __restrict__ W_update, // [256,256]
                    const float* __restrict__ b_update, // [256]
                    const float* __restrict__ gamma,    // [256]
                    const float* __restrict__ beta,     // [256]
                    const float* __restrict__ W_out,    // [10,256]
                    const float* __restrict__ b_out,    // [10]
                    const float* __restrict__ cs_in,    // [1]
                    float* __restrict__ out)            // [512,10]
{
    extern __shared__ float smem[];
    float*  sW  = smem;                                   // WSROWS*WSTRIDE floats (130 KB)
    float4* vsm = (float4*)(smem + WSROWS * WSTRIDE);     // v[j][b] : 256 float4 (4 KB)
    float*  red = (float*)(vsm + HID);                    // 8 warps x 8 partials
    float*  osm = red + 64;                               // 160*4 floats for output stage

    const int tid  = threadIdx.x;
    const int i    = tid;                 // hidden index owned by this thread
    const int b0   = blockIdx.x * NB;     // first batch of this CTA
    const int warp = tid >> 5;
    const int lane = tid & 31;

    // ---- zero this CTA's slot-memory slice (graph replays re-run this) ----
    {
        float4* mz = (float4*)(g_mem + (size_t)b0 * SLOTS * HID);
        const int total = NB * SLOTS * HID / 4;           // 16384 float4
        for (int k = tid; k < total; k += NTH)
            mz[k] = make_float4(0.f, 0.f, 0.f, 0.f);
    }
    // ---- stage W_update rows [0, WSROWS) into padded SMEM ----
    {
        const float4* Wg = (const float4*)W_update;
        for (int idx = tid; idx < WSROWS * (HID / 4); idx += NTH) {
            int r = idx >> 6;       // 64 float4 per row
            int c = idx & 63;
            ((float4*)(sW + r * WSTRIDE))[c] = Wg[idx];
        }
    }

    const float cs   = 1.0f / (1.0f + expf(-cs_in[0]));   // sigmoid(context_strength)
    const float We_i = W_embed[i];
    const float be_i = b_embed[i];
    const float bu_i = b_update[i];
    const float g_i  = gamma[i];
    const float bt_i = beta[i];

    float h[NB];
    float* col[NB];
    const float* xp[NB];
#pragma unroll
    for (int b = 0; b < NB; b++) {
        h[b]   = 0.f;
        col[b] = g_mem + (size_t)(b0 + b) * SLOTS * HID + i;  // private column i
        xp[b]  = x + (size_t)(b0 + b) * TSTEPS;
    }

    __syncthreads();   // zeroed g_mem + staged sW visible block-wide

    for (int t = 0; t < TSTEPS; t++) {
        // ---- attention indices & weights (batch-independent, pointer == t%64) ----
        const int base = t & (SLOTS - 1);
        int   off5[5];
        float wn[5];
        {
            float e[5], s = 0.f;
#pragma unroll
            for (int k = 0; k < 5; k++) {
                int ix = (base + k - 2 + SLOTS) & (SLOTS - 1);
                off5[k] = ix * HID;
                float d = (float)(ix - base);              // delta = index - pointer
                e[k] = expf(-0.125f * d * d);              // exp(-d^2/TAU), max-shift = 0
                s += e[k];
            }
            float inv = 1.0f / s;
#pragma unroll
            for (int k = 0; k < 5; k++) wn[k] = e[k] * inv;
        }

        // ---- phase 1: v[b] = tanh(x*We+be) + cs*context + h[b] ----
        float m[NB][5];
        float v[NB];
#pragma unroll
        for (int b = 0; b < NB; b++) {
            float ctx = 0.f;
#pragma unroll
            for (int k = 0; k < 5; k++) {
                m[b][k] = col[b][off5[k]];                 // own column: no sync needed
                ctx = fmaf(wn[k], m[b][k], ctx);
            }
            v[b] = tanhf(fmaf(xp[b][t], We_i, be_i)) + cs * ctx + h[b];
        }
        vsm[i] = make_float4(v[0], v[1], v[2], v[3]);
        __syncthreads();

        // ---- phase 2: u[b] = dot(W_update[i,:], v[b,:])  (4x reuse per W load) ----
        float u0 = 0.f, u1 = 0.f, u2 = 0.f, u3 = 0.f;
        if (i < WSROWS) {
            const float4* wr = (const float4*)(sW + i * WSTRIDE);
#pragma unroll 8
            for (int j = 0; j < HID / 4; j++) {
                float4 w4 = wr[j];
                float4 va = vsm[4*j+0], vb = vsm[4*j+1], vc = vsm[4*j+2], vd = vsm[4*j+3];
                u0 = fmaf(w4.x, va.x, u0); u1 = fmaf(w4.x, va.y, u1); u2 = fmaf(w4.x, va.z, u2); u3 = fmaf(w4.x, va.w, u3);
                u0 = fmaf(w4.y, vb.x, u0); u1 = fmaf(w4.y, vb.y, u1); u2 = fmaf(w4.y, vb.z, u2); u3 = fmaf(w4.y, vb.w, u3);
                u0 = fmaf(w4.z, vc.x, u0); u1 = fmaf(w4.z, vc.y, u1); u2 = fmaf(w4.z, vc.z, u2); u3 = fmaf(w4.z, vc.w, u3);
                u0 = fmaf(w4.w, vd.x, u0); u1 = fmaf(w4.w, vd.y, u1); u2 = fmaf(w4.w, vd.z, u2); u3 = fmaf(w4.w, vd.w, u3);
            }
        } else {
            const float4* wr = (const float4*)(W_update + (size_t)i * HID);
#pragma unroll 8
            for (int j = 0; j < HID / 4; j++) {
                float4 w4 = __ldg(&wr[j]);
                float4 va = vsm[4*j+0], vb = vsm[4*j+1], vc = vsm[4*j+2], vd = vsm[4*j+3];
                u0 = fmaf(w4.x, va.x, u0); u1 = fmaf(w4.x, va.y, u1); u2 = fmaf(w4.x, va.z, u2); u3 = fmaf(w4.x, va.w, u3);
                u0 = fmaf(w4.y, vb.x, u0); u1 = fmaf(w4.y, vb.y, u1); u2 = fmaf(w4.y, vb.z, u2); u3 = fmaf(w4.y, vb.w, u3);
                u0 = fmaf(w4.z, vc.x, u0); u1 = fmaf(w4.z, vc.y, u1); u2 = fmaf(w4.z, vc.z, u2); u3 = fmaf(w4.z, vc.w, u3);
                u0 = fmaf(w4.w, vd.x, u0); u1 = fmaf(w4.w, vd.y, u1); u2 = fmaf(w4.w, vd.z, u2); u3 = fmaf(w4.w, vd.w, u3);
            }
        }

        float hn[NB];
        hn[0] = tanhf(u0 + bu_i); hn[1] = tanhf(u1 + bu_i);
        hn[2] = tanhf(u2 + bu_i); hn[3] = tanhf(u3 + bu_i);

        // ---- LayerNorm reductions: 8 quantities (sum, sumsq) x 4 batches ----
        float r8[8];
#pragma unroll
        for (int b = 0; b < NB; b++) { r8[b] = hn[b]; r8[4 + b] = hn[b] * hn[b]; }
#pragma unroll
        for (int o = 16; o > 0; o >>= 1) {
#pragma unroll
            for (int q = 0; q < 8; q++)
                r8[q] += __shfl_xor_sync(0xffffffffu, r8[q], o);
        }
        if (lane == 0) {
#pragma unroll
            for (int q = 0; q < 8; q++) red[warp * 8 + q] = r8[q];
        }
        __syncthreads();   // also guards vsm for next-step rewrite

#pragma unroll
        for (int b = 0; b < NB; b++) {
            float s1 = 0.f, s2 = 0.f;
#pragma unroll
            for (int w = 0; w < 8; w++) { s1 += red[w * 8 + b]; s2 += red[w * 8 + 4 + b]; }
            float mu  = s1 * (1.0f / HID);
            float var = fmaf(s2, 1.0f / HID, -mu * mu);
            float hb  = (hn[b] - mu) * rsqrtf(var + EPSV) * g_i + bt_i;
            h[b] = hb;
            // scatter-add into slot memory (reuses m[b][k]; column private -> no sync)
#pragma unroll
            for (int k = 0; k < 5; k++)
                col[b][off5[k]] = fmaf(wn[k], hb, m[b][k]);
        }
    }

    // ---- output: out[b,:] = h[b] @ W_out^T + b_out ----
    vsm[i] = make_float4(h[0], h[1], h[2], h[3]);
    __syncthreads();
    if (tid < 160) {                       // 16 segments x 10 outputs
        int o = tid % 10, seg = tid / 10;
        float a0 = 0.f, a1 = 0.f, a2 = 0.f, a3 = 0.f;
#pragma unroll
        for (int jj = 0; jj < 16; jj++) {
            int ii = seg * 16 + jj;
            float w = W_out[o * HID + ii];
            float4 hh = vsm[ii];
            a0 = fmaf(w, hh.x, a0); a1 = fmaf(w, hh.y, a1);
            a2 = fmaf(w, hh.z, a2); a3 = fmaf(w, hh.w, a3);
        }
        osm[tid * 4 + 0] = a0; osm[tid * 4 + 1] = a1;
        osm[tid * 4 + 2] = a2; osm[tid * 4 + 3] = a3;
    }
    __syncthreads();
    if (tid < NB * 10) {
        int o = tid % 10, b = tid / 10;
        float s = b_out[o];
#pragma unroll
        for (int seg = 0; seg < 16; seg++)
            s += osm[(seg * 10 + o) * 4 + b];
        out[(size_t)(b0 + b) * 10 + o] = s;
    }
}

extern "C" void kernel_launch(void* const* d_in, const int* in_sizes, int n_in,
                              void* d_out, int out_size) {
    (void)in_sizes; (void)n_in; (void)out_size;
    const float* x        = (const float*)d_in[0];
    const float* W_embed  = (const float*)d_in[1];
    const float* b_embed  = (const float*)d_in[2];
    const float* W_update = (const float*)d_in[3];
    const float* b_update = (const float*)d_in[4];
    const float* gamma    = (const float*)d_in[5];
    const float* beta     = (const float*)d_in[6];
    const float* W_out    = (const float*)d_in[7];
    const float* b_out    = (const float*)d_in[8];
    const float* cs       = (const float*)d_in[9];

    const size_t SMEM_BYTES =
        (size_t)(WSROWS * WSTRIDE + HID * 4 + 64 + 640) * sizeof(float); // 140032 B

    cudaFuncSetAttribute(postnorm_rnn_kernel,
                         cudaFuncAttributeMaxDynamicSharedMemorySize,
                         (int)SMEM_BYTES);

    postnorm_rnn_kernel<<<BATCH / NB, NTH, SMEM_BYTES>>>(
        x, W_embed, b_embed, W_update, b_update, gamma, beta,
        W_out, b_out, cs, (float*)d_out);
}

// round 6
// speedup vs baseline: 1.0532x; 1.0532x over previous
#include <cuda_runtime.h>
#include <math.h>

#define HID     256
#define SLOTS   64
#define NB      4
#define TSTEPS  256
#define BATCH   512
#define WSROWS  128          // W_update rows cached in SMEM
#define WSTRIDE 260          // 256 + 4 pad: LDS.128 conflict-free (stride%32==4)
#define NTH     256
#define EPSV    1e-5f

// Slot-memory scratch: 512 x 64 x 256 fp32 = 32 MB (L2-resident)
__device__ float g_mem[(size_t)BATCH * SLOTS * HID];

__device__ __forceinline__ float fast_tanh(float x) {
    // tanh(x) = 1 - 2/(exp(2x)+1); MUFU.EX2 + MUFU.RCP, ~few-ulp accurate,
    // graceful at +/-inf (exp->inf => 1, exp->0 => -1)
    float e = __expf(2.0f * x);
    return 1.0f - __fdividef(2.0f, e + 1.0f);
}

#define FFMA2(acc, a, b) \
    asm("fma.rn.f32x2 %0, %1, %2, %0;" : "+l"(acc) : "l"(a), "l"(b))

__global__ void __launch_bounds__(NTH, 1)
postnorm_rnn_kernel(const float* __restrict__ x,        // [512,256,1]
                    const float* __restrict__ W_embed,  // [256]
                    const float* __restrict__ b_embed,  // [256]
                    const float* __restrict__ W_update, // [256,256]
                    const float* __restrict__ b_update, // [256]
                    const float* __restrict__ gamma,    // [256]
                    const float* __restrict__ beta,     // [256]
                    const float* __restrict__ W_out,    // [10,256]
                    const float* __restrict__ b_out,    // [10]
                    const float* __restrict__ cs_in,    // [1]
                    float* __restrict__ out)            // [512,10]
{
    extern __shared__ float smem[];
    float* sW   = smem;                          // 128*260      = 33280 f
    float* vrow = sW + WSROWS * WSTRIDE;         // [b][j] 4*256 =  1024 f
    float* xsm  = vrow + NB * HID;               // [b][t] 4*256 =  1024 f
    float* wtab = xsm + NB * TSTEPS;             // [base][k] 64*5 = 320 f
    float* red  = wtab + 320;                    // 8 warps x 8    =  64 f
    float* osm  = red + 64;                      // 160*4          = 640 f

    const int tid  = threadIdx.x;
    const int i    = tid;                 // hidden row owned by this thread
    const int b0   = blockIdx.x * NB;
    const int warp = tid >> 5;
    const int lane = tid & 31;

    // ---- zero this CTA's slot-memory slice (graph replays re-run this) ----
    {
        float4* mz = (float4*)(g_mem + (size_t)b0 * SLOTS * HID);
        for (int k = tid; k < NB * SLOTS * HID / 4; k += NTH)
            mz[k] = make_float4(0.f, 0.f, 0.f, 0.f);
    }
    // ---- stage W_update rows [0,128) into padded SMEM ----
    {
        const float4* Wg = (const float4*)W_update;
        for (int idx = tid; idx < WSROWS * (HID / 4); idx += NTH) {
            int r = idx >> 6, c = idx & 63;
            ((float4*)(sW + r * WSTRIDE))[c] = Wg[idx];
        }
    }
    // ---- stage x for this CTA's 4 batches: xsm[b][t] ----
    {
        int b  = tid >> 6;           // 0..3
        int t4 = tid & 63;           // 0..63 float4 per batch
        ((float4*)xsm)[tid] =
            ((const float4*)(x + (size_t)(b0 + b) * TSTEPS))[t4];
    }
    // ---- precompute softmax attention-weight table (base-dependent only) ----
    if (tid < SLOTS) {
        int base = tid;
        float e[5], s = 0.f;
#pragma unroll
        for (int k = 0; k < 5; k++) {
            int ix = (base + k - 2 + SLOTS) & (SLOTS - 1);
            float d = (float)(ix - base);          // delta = index - pointer
            e[k] = expf(-0.125f * d * d);          // exp(-d^2/TAU), max-shift=0
            s += e[k];
        }
        float inv = 1.0f / s;
#pragma unroll
        for (int k = 0; k < 5; k++) wtab[base * 5 + k] = e[k] * inv;
    }

    const float cs   = 1.0f / (1.0f + expf(-cs_in[0]));
    const float We_i = W_embed[i];
    const float be_i = b_embed[i];
    const float bu_i = b_update[i];
    const float g_i  = gamma[i];
    const float bt_i = beta[i];

    float h[NB];
    float m[NB][5];                  // register-resident 5-slot window
    float* col[NB];
#pragma unroll
    for (int b = 0; b < NB; b++) {
        h[b] = 0.f;
        col[b] = g_mem + (size_t)(b0 + b) * SLOTS * HID + i;
#pragma unroll
        for (int k = 0; k < 5; k++) m[b][k] = 0.f;   // slots {62,63,0,1,2}: zero
    }

    __syncthreads();

    for (int t = 0; t < TSTEPS; t++) {
        const int base  = t & (SLOTS - 1);
        const int s_in  = ((base + 3) & (SLOTS - 1)) * HID;   // slot entering window
        const int s_out = ((base + 62) & (SLOTS - 1)) * HID;  // slot leaving window

        // prefetch entering slot early: ~full step of latency slack
        float pf[NB];
#pragma unroll
        for (int b = 0; b < NB; b++) pf[b] = col[b][s_in];

        float wn[5];
#pragma unroll
        for (int k = 0; k < 5; k++) wn[k] = wtab[base * 5 + k];

        // ---- phase 1: v[b] = tanh(x*We+be) + cs*ctx + h[b] (all registers) ----
#pragma unroll
        for (int b = 0; b < NB; b++) {
            float ctx = 0.f;
#pragma unroll
            for (int k = 0; k < 5; k++) ctx = fmaf(wn[k], m[b][k], ctx);
            float v = fast_tanh(fmaf(xsm[b * TSTEPS + t], We_i, be_i))
                      + cs * ctx + h[b];
            vrow[b * HID + i] = v;
        }
        __syncthreads();

        // ---- phase 2: u[b] = W_update[i,:] . v[b,:]  via packed f32x2 ----
        unsigned long long acc0 = 0ull, acc1 = 0ull, acc2 = 0ull, acc3 = 0ull;
        if (i < WSROWS) {
            const ulonglong2* wr = (const ulonglong2*)(sW + i * WSTRIDE);
#pragma unroll 8
            for (int j = 0; j < HID / 4; j++) {
                ulonglong2 w2 = wr[j];
                ulonglong2 v0 = *(const ulonglong2*)(vrow + 0 * HID + 4 * j);
                ulonglong2 v1 = *(const ulonglong2*)(vrow + 1 * HID + 4 * j);
                ulonglong2 v2 = *(const ulonglong2*)(vrow + 2 * HID + 4 * j);
                ulonglong2 v3 = *(const ulonglong2*)(vrow + 3 * HID + 4 * j);
                FFMA2(acc0, w2.x, v0.x); FFMA2(acc0, w2.y, v0.y);
                FFMA2(acc1, w2.x, v1.x); FFMA2(acc1, w2.y, v1.y);
                FFMA2(acc2, w2.x, v2.x); FFMA2(acc2, w2.y, v2.y);
                FFMA2(acc3, w2.x, v3.x); FFMA2(acc3, w2.y, v3.y);
            }
        } else {
            const ulonglong2* wr = (const ulonglong2*)(W_update + (size_t)i * HID);
#pragma unroll 8
            for (int j = 0; j < HID / 4; j++) {
                ulonglong2 w2 = __ldg(&wr[j]);
                ulonglong2 v0 = *(const ulonglong2*)(vrow + 0 * HID + 4 * j);
                ulonglong2 v1 = *(const ulonglong2*)(vrow + 1 * HID + 4 * j);
                ulonglong2 v2 = *(const ulonglong2*)(vrow + 2 * HID + 4 * j);
                ulonglong2 v3 = *(const ulonglong2*)(vrow + 3 * HID + 4 * j);
                FFMA2(acc0, w2.x, v0.x); FFMA2(acc0, w2.y, v0.y);
                FFMA2(acc1, w2.x, v1.x); FFMA2(acc1, w2.y, v1.y);
                FFMA2(acc2, w2.x, v2.x); FFMA2(acc2, w2.y, v2.y);
                FFMA2(acc3, w2.x, v3.x); FFMA2(acc3, w2.y, v3.y);
            }
        }

        float hn[NB];
        {
            unsigned long long a[4] = {acc0, acc1, acc2, acc3};
#pragma unroll
            for (int b = 0; b < NB; b++) {
                float lo = __uint_as_float((unsigned)(a[b] & 0xffffffffu));
                float hi = __uint_as_float((unsigned)(a[b] >> 32));
                hn[b] = fast_tanh(lo + hi + bu_i);
            }
        }

        // ---- LayerNorm reductions: (sum, sumsq) x 4 batches ----
        float r8[8];
#pragma unroll
        for (int b = 0; b < NB; b++) { r8[b] = hn[b]; r8[4 + b] = hn[b] * hn[b]; }
#pragma unroll
        for (int o = 16; o > 0; o >>= 1) {
#pragma unroll
            for (int q = 0; q < 8; q++)
                r8[q] += __shfl_xor_sync(0xffffffffu, r8[q], o);
        }
        if (lane == 0) {
#pragma unroll
            for (int q = 0; q < 8; q++) red[warp * 8 + q] = r8[q];
        }
        __syncthreads();   // also guards vrow for next-step rewrite

#pragma unroll
        for (int b = 0; b < NB; b++) {
            float s1 = 0.f, s2 = 0.f;
#pragma unroll
            for (int w = 0; w < 8; w++) { s1 += red[w * 8 + b]; s2 += red[w * 8 + 4 + b]; }
            float mu  = s1 * (1.0f / HID);
            float var = fmaf(s2, 1.0f / HID, -mu * mu);
            float hb  = (hn[b] - mu) * rsqrtf(var + EPSV) * g_i + bt_i;
            h[b] = hb;
            // flush leaving slot's final value; shift window; admit prefetched slot
            col[b][s_out] = fmaf(wn[0], hb, m[b][0]);
            m[b][0] = fmaf(wn[1], hb, m[b][1]);
            m[b][1] = fmaf(wn[2], hb, m[b][2]);
            m[b][2] = fmaf(wn[3], hb, m[b][3]);
            m[b][3] = fmaf(wn[4], hb, m[b][4]);
            m[b][4] = pf[b];
        }
    }

    // ---- output: out[b,:] = h[b] @ W_out^T + b_out ----
#pragma unroll
    for (int b = 0; b < NB; b++) vrow[b * HID + i] = h[b];
    __syncthreads();
    if (tid < 160) {                       // 16 segments x 10 outputs
        int o = tid % 10, seg = tid / 10;
        float a0 = 0.f, a1 = 0.f, a2 = 0.f, a3 = 0.f;
#pragma unroll
        for (int jj = 0; jj < 16; jj++) {
            int ii = seg * 16 + jj;
            float w = W_out[o * HID + ii];
            a0 = fmaf(w, vrow[0 * HID + ii], a0);
            a1 = fmaf(w, vrow[1 * HID + ii], a1);
            a2 = fmaf(w, vrow[2 * HID + ii], a2);
            a3 = fmaf(w, vrow[3 * HID + ii], a3);
        }
        osm[tid * 4 + 0] = a0; osm[tid * 4 + 1] = a1;
        osm[tid * 4 + 2] = a2; osm[tid * 4 + 3] = a3;
    }
    __syncthreads();
    if (tid < NB * 10) {
        int o = tid % 10, b = tid / 10;
        float s = b_out[o];
#pragma unroll
        for (int seg = 0; seg < 16; seg++)
            s += osm[(seg * 10 + o) * 4 + b];
        out[(size_t)(b0 + b) * 10 + o] = s;
    }
}

extern "C" void kernel_launch(void* const* d_in, const int* in_sizes, int n_in,
                              void* d_out, int out_size) {
    (void)in_sizes; (void)n_in; (void)out_size;
    const float* x        = (const float*)d_in[0];
    const float* W_embed  = (const float*)d_in[1];
    const float* b_embed  = (const float*)d_in[2];
    const float* W_update = (const float*)d_in[3];
    const float* b_update = (const float*)d_in[4];
    const float* gamma    = (const float*)d_in[5];
    const float* beta     = (const float*)d_in[6];
    const float* W_out    = (const float*)d_in[7];
    const float* b_out    = (const float*)d_in[8];
    const float* cs       = (const float*)d_in[9];

    const size_t SMEM_BYTES =
        (size_t)(WSROWS * WSTRIDE + NB * HID + NB * TSTEPS + 320 + 64 + 640)
        * sizeof(float);   // 145,152 B

    cudaFuncSetAttribute(postnorm_rnn_kernel,
                         cudaFuncAttributeMaxDynamicSharedMemorySize,
                         (int)SMEM_BYTES);

    postnorm_rnn_kernel<<<BATCH / NB, NTH, SMEM_BYTES>>>(
        x, W_embed, b_embed, W_update, b_update, gamma, beta,
        W_out, b_out, cs, (float*)d_out);
}

// round 7
// speedup vs baseline: 2.3881x; 2.2674x over previous
#include <cuda_runtime.h>
#include <math.h>

#define HID     256
#define SLOTS   64
#define NB      4
#define TSTEPS  256
#define BATCH   512
#define WSROWS  192          // W_update rows cached in SMEM (multiple of 4)
#define WSTRIDE 260          // 256 + 4 pad: conflict-free LDS.128
#define NTH     256
#define EPSV    1e-5f

// Slot-memory scratch: 512 x 64 x 256 fp32 = 32 MB (L2-resident)
__device__ float g_mem[(size_t)BATCH * SLOTS * HID];

__device__ __forceinline__ float fast_tanh(float x) {
    float e = __expf(2.0f * x);                 // MUFU.EX2 path
    return 1.0f - __fdividef(2.0f, e + 1.0f);   // MUFU.RCP path
}

#define FFMA2(acc, a, b) \
    asm("fma.rn.f32x2 %0, %1, %2, %0;" : "+l"(acc) : "l"(a), "l"(b))

__global__ void __launch_bounds__(NTH, 1)
postnorm_rnn_kernel(const float* __restrict__ x,        // [512,256,1]
                    const float* __restrict__ W_embed,  // [256]
                    const float* __restrict__ b_embed,  // [256]
                    const float* __restrict__ W_update, // [256,256]
                    const float* __restrict__ b_update, // [256]
                    const float* __restrict__ gamma,    // [256]
                    const float* __restrict__ beta,     // [256]
                    const float* __restrict__ W_out,    // [10,256]
                    const float* __restrict__ b_out,    // [10]
                    const float* __restrict__ cs_in,    // [1]
                    float* __restrict__ out)            // [512,10]
{
    extern __shared__ float smem[];
    float* sW   = smem;                          // 192*260       = 49920 f
    float* vrow = sW + WSROWS * WSTRIDE;         // [b][j] 4*256  =  1024 f
    float* xsm  = vrow + NB * HID;               // [b][t] 4*256  =  1024 f
    float* wtab = xsm + NB * TSTEPS;             // [base][k] 64*5 =  320 f
    float* red  = wtab + 320;                    // 8 warps x 8   =    64 f
    float* osm  = red + 64;                      // 160*4         =   640 f

    const int tid   = threadIdx.x;
    const int i     = tid;                // hidden index owned (phase1/LN/mem)
    const int b0    = blockIdx.x * NB;
    const int warp  = tid >> 5;
    const int lane  = tid & 31;
    const int s     = tid & 3;            // k-slice id
    const int rbase = tid & ~3;           // row block: rows rbase..rbase+3
    const int sK    = s * 4;              // k offset within each 16-float group

    // ---- zero this CTA's slot-memory slice ----
    {
        float4* mz = (float4*)(g_mem + (size_t)b0 * SLOTS * HID);
        for (int k = tid; k < NB * SLOTS * HID / 4; k += NTH)
            mz[k] = make_float4(0.f, 0.f, 0.f, 0.f);
    }
    // ---- stage W_update rows [0,192) into padded SMEM ----
    {
        const float4* Wg = (const float4*)W_update;
        for (int idx = tid; idx < WSROWS * (HID / 4); idx += NTH) {
            int r = idx >> 6, c = idx & 63;
            ((float4*)(sW + r * WSTRIDE))[c] = Wg[idx];
        }
    }
    // ---- stage x: xsm[b][t] ----
    {
        int b = tid >> 6, t4 = tid & 63;
        ((float4*)xsm)[tid] =
            ((const float4*)(x + (size_t)(b0 + b) * TSTEPS))[t4];
    }
    // ---- precompute softmax attention-weight table ----
    if (tid < SLOTS) {
        int base = tid;
        float e[5], sum = 0.f;
#pragma unroll
        for (int k = 0; k < 5; k++) {
            int ix = (base + k - 2 + SLOTS) & (SLOTS - 1);
            float d = (float)(ix - base);
            e[k] = expf(-0.125f * d * d);
            sum += e[k];
        }
        float inv = 1.0f / sum;
#pragma unroll
        for (int k = 0; k < 5; k++) wtab[base * 5 + k] = e[k] * inv;
    }

    const float cs   = 1.0f / (1.0f + expf(-cs_in[0]));
    const float We_i = W_embed[i];
    const float be_i = b_embed[i];
    const float bu_i = b_update[i];
    const float g_i  = gamma[i];
    const float bt_i = beta[i];

    float h[NB];
    float m[NB][5];                  // register-resident 5-slot window
    float* col[NB];
#pragma unroll
    for (int b = 0; b < NB; b++) {
        h[b] = 0.f;
        col[b] = g_mem + (size_t)(b0 + b) * SLOTS * HID + i;
#pragma unroll
        for (int k = 0; k < 5; k++) m[b][k] = 0.f;
    }

    // W row pointers for this thread's 4 rows over its k-slice
    const bool insm = (rbase < WSROWS);
    const float* wp[4];
#pragma unroll
    for (int r = 0; r < 4; r++)
        wp[r] = insm ? (sW + (rbase + r) * WSTRIDE + sK)
                     : (W_update + (size_t)(rbase + r) * HID + sK);

    __syncthreads();

    for (int t = 0; t < TSTEPS; t++) {
        const int base  = t & (SLOTS - 1);
        const int s_in  = ((base + 3)  & (SLOTS - 1)) * HID;
        const int s_out = ((base + 62) & (SLOTS - 1)) * HID;

        float pf[NB];
#pragma unroll
        for (int b = 0; b < NB; b++) pf[b] = col[b][s_in];   // prefetch, ~1 step slack

        float wn[5];
#pragma unroll
        for (int k = 0; k < 5; k++) wn[k] = wtab[base * 5 + k];

        // ---- phase 1: v[b] = tanh(x*We+be) + cs*ctx + h[b] ----
#pragma unroll
        for (int b = 0; b < NB; b++) {
            float ctx = 0.f;
#pragma unroll
            for (int k = 0; k < 5; k++) ctx = fmaf(wn[k], m[b][k], ctx);
            float v = fast_tanh(fmaf(xsm[b * TSTEPS + t], We_i, be_i))
                      + cs * ctx + h[b];
            vrow[b * HID + i] = v;
        }
        __syncthreads();

        // ---- phase 2: partial dots, rows rbase..rbase+3, k = {16*jj + sK + e} ----
        unsigned long long acc[4][4];   // [row][batch], packed k-pairs
#pragma unroll
        for (int r = 0; r < 4; r++)
#pragma unroll
            for (int b = 0; b < 4; b++) acc[r][b] = 0ull;

        if (insm) {
#pragma unroll
            for (int jj = 0; jj < 16; jj++) {
                ulonglong2 w0 = *(const ulonglong2*)(wp[0] + jj * 16);
                ulonglong2 w1 = *(const ulonglong2*)(wp[1] + jj * 16);
                ulonglong2 w2 = *(const ulonglong2*)(wp[2] + jj * 16);
                ulonglong2 w3 = *(const ulonglong2*)(wp[3] + jj * 16);
                ulonglong2 v0 = *(const ulonglong2*)(vrow + 0 * HID + sK + jj * 16);
                ulonglong2 v1 = *(const ulonglong2*)(vrow + 1 * HID + sK + jj * 16);
                ulonglong2 v2 = *(const ulonglong2*)(vrow + 2 * HID + sK + jj * 16);
                ulonglong2 v3 = *(const ulonglong2*)(vrow + 3 * HID + sK + jj * 16);
                FFMA2(acc[0][0], w0.x, v0.x); FFMA2(acc[0][0], w0.y, v0.y);
                FFMA2(acc[0][1], w0.x, v1.x); FFMA2(acc[0][1], w0.y, v1.y);
                FFMA2(acc[0][2], w0.x, v2.x); FFMA2(acc[0][2], w0.y, v2.y);
                FFMA2(acc[0][3], w0.x, v3.x); FFMA2(acc[0][3], w0.y, v3.y);
                FFMA2(acc[1][0], w1.x, v0.x); FFMA2(acc[1][0], w1.y, v0.y);
                FFMA2(acc[1][1], w1.x, v1.x); FFMA2(acc[1][1], w1.y, v1.y);
                FFMA2(acc[1][2], w1.x, v2.x); FFMA2(acc[1][2], w1.y, v2.y);
                FFMA2(acc[1][3], w1.x, v3.x); FFMA2(acc[1][3], w1.y, v3.y);
                FFMA2(acc[2][0], w2.x, v0.x); FFMA2(acc[2][0], w2.y, v0.y);
                FFMA2(acc[2][1], w2.x, v1.x); FFMA2(acc[2][1], w2.y, v1.y);
                FFMA2(acc[2][2], w2.x, v2.x); FFMA2(acc[2][2], w2.y, v2.y);
                FFMA2(acc[2][3], w2.x, v3.x); FFMA2(acc[2][3], w2.y, v3.y);
                FFMA2(acc[3][0], w3.x, v0.x); FFMA2(acc[3][0], w3.y, v0.y);
                FFMA2(acc[3][1], w3.x, v1.x); FFMA2(acc[3][1], w3.y, v1.y);
                FFMA2(acc[3][2], w3.x, v2.x); FFMA2(acc[3][2], w3.y, v2.y);
                FFMA2(acc[3][3], w3.x, v3.x); FFMA2(acc[3][3], w3.y, v3.y);
            }
        } else {
#pragma unroll
            for (int jj = 0; jj < 16; jj++) {
                ulonglong2 w0 = __ldg((const ulonglong2*)(wp[0] + jj * 16));
                ulonglong2 w1 = __ldg((const ulonglong2*)(wp[1] + jj * 16));
                ulonglong2 w2 = __ldg((const ulonglong2*)(wp[2] + jj * 16));
                ulonglong2 w3 = __ldg((const ulonglong2*)(wp[3] + jj * 16));
                ulonglong2 v0 = *(const ulonglong2*)(vrow + 0 * HID + sK + jj * 16);
                ulonglong2 v1 = *(const ulonglong2*)(vrow + 1 * HID + sK + jj * 16);
                ulonglong2 v2 = *(const ulonglong2*)(vrow + 2 * HID + sK + jj * 16);
                ulonglong2 v3 = *(const ulonglong2*)(vrow + 3 * HID + sK + jj * 16);
                FFMA2(acc[0][0], w0.x, v0.x); FFMA2(acc[0][0], w0.y, v0.y);
                FFMA2(acc[0][1], w0.x, v1.x); FFMA2(acc[0][1], w0.y, v1.y);
                FFMA2(acc[0][2], w0.x, v2.x); FFMA2(acc[0][2], w0.y, v2.y);
                FFMA2(acc[0][3], w0.x, v3.x); FFMA2(acc[0][3], w0.y, v3.y);
                FFMA2(acc[1][0], w1.x, v0.x); FFMA2(acc[1][0], w1.y, v0.y);
                FFMA2(acc[1][1], w1.x, v1.x); FFMA2(acc[1][1], w1.y, v1.y);
                FFMA2(acc[1][2], w1.x, v2.x); FFMA2(acc[1][2], w1.y, v2.y);
                FFMA2(acc[1][3], w1.x, v3.x); FFMA2(acc[1][3], w1.y, v3.y);
                FFMA2(acc[2][0], w2.x, v0.x); FFMA2(acc[2][0], w2.y, v0.y);
                FFMA2(acc[2][1], w2.x, v1.x); FFMA2(acc[2][1], w2.y, v1.y);
                FFMA2(acc[2][2], w2.x, v2.x); FFMA2(acc[2][2], w2.y, v2.y);
                FFMA2(acc[2][3], w2.x, v3.x); FFMA2(acc[2][3], w2.y, v3.y);
                FFMA2(acc[3][0], w3.x, v0.x); FFMA2(acc[3][0], w3.y, v0.y);
                FFMA2(acc[3][1], w3.x, v1.x); FFMA2(acc[3][1], w3.y, v1.y);
                FFMA2(acc[3][2], w3.x, v2.x); FFMA2(acc[3][2], w3.y, v2.y);
                FFMA2(acc[3][3], w3.x, v3.x); FFMA2(acc[3][3], w3.y, v3.y);
            }
        }

        // ---- unpack + allreduce partials across the 4 k-slices (lanes xor 1,2) ----
        float P[4][4];
#pragma unroll
        for (int r = 0; r < 4; r++)
#pragma unroll
            for (int b = 0; b < 4; b++) {
                float lo = __uint_as_float((unsigned)(acc[r][b] & 0xffffffffu));
                float hi = __uint_as_float((unsigned)(acc[r][b] >> 32));
                P[r][b] = lo + hi;
            }
#pragma unroll
        for (int o = 1; o <= 2; o <<= 1)
#pragma unroll
            for (int r = 0; r < 4; r++)
#pragma unroll
                for (int b = 0; b < 4; b++)
                    P[r][b] += __shfl_xor_sync(0xffffffffu, P[r][b], o);

        // thread picks its own row (rbase + s == tid)
        float hn[NB];
#pragma unroll
        for (int b = 0; b < 4; b++) {
            float t0 = (s & 1) ? P[1][b] : P[0][b];
            float t1 = (s & 1) ? P[3][b] : P[2][b];
            float u  = (s & 2) ? t1 : t0;
            hn[b] = fast_tanh(u + bu_i);
        }

        // ---- LayerNorm reductions: (sum, sumsq) x 4 batches ----
        float r8[8];
#pragma unroll
        for (int b = 0; b < NB; b++) { r8[b] = hn[b]; r8[4 + b] = hn[b] * hn[b]; }
#pragma unroll
        for (int o = 16; o > 0; o >>= 1)
#pragma unroll
            for (int q = 0; q < 8; q++)
                r8[q] += __shfl_xor_sync(0xffffffffu, r8[q], o);
        if (lane == 0) {
#pragma unroll
            for (int q = 0; q < 8; q++) red[warp * 8 + q] = r8[q];
        }
        __syncthreads();   // also guards vrow for next-step rewrite

#pragma unroll
        for (int b = 0; b < NB; b++) {
            float s1 = 0.f, s2 = 0.f;
#pragma unroll
            for (int w = 0; w < 8; w++) { s1 += red[w * 8 + b]; s2 += red[w * 8 + 4 + b]; }
            float mu  = s1 * (1.0f / HID);
            float var = fmaf(s2, 1.0f / HID, -mu * mu);
            float hb  = (hn[b] - mu) * rsqrtf(var + EPSV) * g_i + bt_i;
            h[b] = hb;
            col[b][s_out] = fmaf(wn[0], hb, m[b][0]);   // flush leaving slot
            m[b][0] = fmaf(wn[1], hb, m[b][1]);
            m[b][1] = fmaf(wn[2], hb, m[b][2]);
            m[b][2] = fmaf(wn[3], hb, m[b][3]);
            m[b][3] = fmaf(wn[4], hb, m[b][4]);
            m[b][4] = pf[b];
        }
    }

    // ---- output: out[b,:] = h[b] @ W_out^T + b_out ----
#pragma unroll
    for (int b = 0; b < NB; b++) vrow[b * HID + i] = h[b];
    __syncthreads();
    if (tid < 160) {                       // 16 segments x 10 outputs
        int o = tid % 10, seg = tid / 10;
        float a0 = 0.f, a1 = 0.f, a2 = 0.f, a3 = 0.f;
#pragma unroll
        for (int jj = 0; jj < 16; jj++) {
            int ii = seg * 16 + jj;
            float w = W_out[o * HID + ii];
            a0 = fmaf(w, vrow[0 * HID + ii], a0);
            a1 = fmaf(w, vrow[1 * HID + ii], a1);
            a2 = fmaf(w, vrow[2 * HID + ii], a2);
            a3 = fmaf(w, vrow[3 * HID + ii], a3);
        }
        osm[tid * 4 + 0] = a0; osm[tid * 4 + 1] = a1;
        osm[tid * 4 + 2] = a2; osm[tid * 4 + 3] = a3;
    }
    __syncthreads();
    if (tid < NB * 10) {
        int o = tid % 10, b = tid / 10;
        float sum = b_out[o];
#pragma unroll
        for (int seg = 0; seg < 16; seg++)
            sum += osm[(seg * 10 + o) * 4 + b];
        out[(size_t)(b0 + b) * 10 + o] = sum;
    }
}

extern "C" void kernel_launch(void* const* d_in, const int* in_sizes, int n_in,
                              void* d_out, int out_size) {
    (void)in_sizes; (void)n_in; (void)out_size;
    const float* x        = (const float*)d_in[0];
    const float* W_embed  = (const float*)d_in[1];
    const float* b_embed  = (const float*)d_in[2];
    const float* W_update = (const float*)d_in[3];
    const float* b_update = (const float*)d_in[4];
    const float* gamma    = (const float*)d_in[5];
    const float* beta     = (const float*)d_in[6];
    const float* W_out    = (const float*)d_in[7];
    const float* b_out    = (const float*)d_in[8];
    const float* cs       = (const float*)d_in[9];

    const size_t SMEM_BYTES =
        (size_t)(WSROWS * WSTRIDE + NB * HID + NB * TSTEPS + 320 + 64 + 640)
        * sizeof(float);   // 211,968 B

    cudaFuncSetAttribute(postnorm_rnn_kernel,
                         cudaFuncAttributeMaxDynamicSharedMemorySize,
                         (int)SMEM_BYTES);

    postnorm_rnn_kernel<<<BATCH / NB, NTH, SMEM_BYTES>>>(
        x, W_embed, b_embed, W_update, b_update, gamma, beta,
        W_out, b_out, cs, (float*)d_out);
}